// round 13
// baseline (speedup 1.0000x reference)
#include <cuda_runtime.h>
#include <cuda_bf16.h>

// TopKPool_16372415332892
// out[b] = (1/K) * sum_{topK rows} x[row] * tanh((x[row].w)/||w||)
// B=256, N=512, D=256, K=256. edge_index/batch dead inputs.

#define BB 256
#define NN 512
#define DD 256
#define KK 256

__device__ float g_score[BB * NN];     // raw dot products (selection monotone in this)
__device__ int2  g_sel[BB * KK];       // {node idx, gate bits}, compacted by node order
__device__ float g_part[BB * 4 * DD];  // gather partials (4 chunks/graph)
__device__ int   g_cnt[BB];            // gather->fold arrival counters (self-resetting)
__device__ int   g_flag[BB];           // g_sel-ready flags (self-resetting)

// ---------------- Kernel 1: scores (2 rows/warp, wide grid) ----------------
// grid = B*N/16 = 8192 blocks, 256 threads. Block 0 re-zeros sync state.
__global__ __launch_bounds__(256)
void score_kernel(const float* __restrict__ x, const float* __restrict__ w)
{
    if (blockIdx.x == 0 && threadIdx.x < BB) {
        g_cnt[threadIdx.x]  = 0;
        g_flag[threadIdx.x] = 0;
    }

    const int lane = threadIdx.x & 31;
    const int warp = threadIdx.x >> 5;
    const int row0 = blockIdx.x * 16 + warp * 2;

    const float4 wa = *reinterpret_cast<const float4*>(w + lane * 4);
    const float4 wb = *reinterpret_cast<const float4*>(w + 128 + lane * 4);

    const float* r0 = x + (size_t)row0 * DD;
    const float* r1 = r0 + DD;
    const float4 a0 = *reinterpret_cast<const float4*>(r0 + lane * 4);
    const float4 c0 = *reinterpret_cast<const float4*>(r0 + 128 + lane * 4);
    const float4 a1 = *reinterpret_cast<const float4*>(r1 + lane * 4);
    const float4 c1 = *reinterpret_cast<const float4*>(r1 + 128 + lane * 4);

    float d0 = a0.x * wa.x + a0.y * wa.y + a0.z * wa.z + a0.w * wa.w
             + c0.x * wb.x + c0.y * wb.y + c0.z * wb.z + c0.w * wb.w;
    float d1 = a1.x * wa.x + a1.y * wa.y + a1.z * wa.z + a1.w * wa.w
             + c1.x * wb.x + c1.y * wb.y + c1.z * wb.z + c1.w * wb.w;
    #pragma unroll
    for (int o = 16; o; o >>= 1) {
        d0 += __shfl_xor_sync(0xffffffffu, d0, o);
        d1 += __shfl_xor_sync(0xffffffffu, d1, o);
    }
    if (lane == 0) {
        g_score[row0]     = d0;
        g_score[row0 + 1] = d1;
    }
}

// ---------------- Kernel 2: fused select + gather + fold ----------------
// grid = B*4 blocks, 256 threads; all 1024 blocks co-resident (8/SM * 148 >= 1024),
// so the intra-kernel spin on g_flag cannot deadlock.
// c==0 block: radix top-K select (2 nodes/thread), publish g_sel, raise flag.
// c!=0 blocks: spin on flag. Then all 4 chunks gather 64 rows each; last
// arriver folds partials (fixed slots, fixed order -> deterministic) into out.
__global__ __launch_bounds__(256)
void select_gather_kernel(const float* __restrict__ x,
                          const float* __restrict__ w,
                          float* __restrict__ out)
{
    __shared__ int2 s_sel[64];
    __shared__ int  s_last;

    const int tid  = threadIdx.x;
    const int lane = tid & 31;
    const int warp = tid >> 5;
    const int b    = blockIdx.x >> 2;
    const int c    = blockIdx.x & 3;

    if (c == 0) {
        // ---- radix top-K select: 256 threads, nodes tid and tid+256 ----
        __shared__ unsigned hist[256];
        __shared__ unsigned sscan[256];   // sscan[v] = # active nodes with byte >= v
        __shared__ unsigned s_t, s_gt, s_remk;
        __shared__ int s_wA[8], s_wB[8], s_pA[8], s_pB[8];
        __shared__ float s_inv;

        if (warp == 0) {
            float ssq = 0.f;
            #pragma unroll
            for (int i = 0; i < 8; i++) { float v = w[lane + i * 32]; ssq += v * v; }
            #pragma unroll
            for (int o = 16; o; o >>= 1) ssq += __shfl_xor_sync(0xffffffffu, ssq, o);
            if (lane == 0) s_inv = rsqrtf(ssq);
        }
        if (tid == 0) s_remk = KK;

        const float* sc = g_score + b * NN;
        const float s0v = sc[tid];
        const float s1v = sc[tid + 256];
        const unsigned bits0 = __float_as_uint(s0v);
        const unsigned bits1 = __float_as_uint(s1v);
        const unsigned key0 = (bits0 & 0x80000000u) ? ~bits0 : (bits0 | 0x80000000u);
        const unsigned key1 = (bits1 & 0x80000000u) ? ~bits1 : (bits1 | 0x80000000u);

        bool act0 = true, act1 = true, sel0 = false, sel1 = false;

        #pragma unroll
        for (int pass = 0; pass < 4; ++pass) {
            hist[tid] = 0u;
            __syncthreads();
            const unsigned b0 = (key0 >> (24 - 8 * pass)) & 0xFFu;
            const unsigned b1 = (key1 >> (24 - 8 * pass)) & 0xFFu;
            if (act0) atomicAdd(&hist[b0], 1u);
            if (act1) atomicAdd(&hist[b1], 1u);
            __syncthreads();

            // suffix scan of hist by warp 0: lane l owns bins [8l, 8l+8)
            if (warp == 0) {
                unsigned tot = 0;
                #pragma unroll
                for (int j = 0; j < 8; j++) tot += hist[lane * 8 + j];
                unsigned suf = tot;
                #pragma unroll
                for (int o = 1; o < 32; o <<= 1) {
                    unsigned t2 = __shfl_down_sync(0xffffffffu, suf, o);
                    if (lane + o < 32) suf += t2;
                }
                unsigned run = suf - tot;
                #pragma unroll
                for (int j = 7; j >= 0; --j) {
                    run += hist[lane * 8 + j];
                    sscan[lane * 8 + j] = run;
                }
            }
            __syncthreads();

            const unsigned remk = s_remk;
            {
                const unsigned ge = sscan[tid];
                const unsigned gt = (tid == 255) ? 0u : sscan[tid + 1];
                if (ge >= remk && gt < remk) { s_t = (unsigned)tid; s_gt = gt; }
            }
            __syncthreads();

            const unsigned t = s_t;
            if (act0) {
                if (b0 > t)      { sel0 = true; act0 = false; }
                else if (b0 < t) { act0 = false; }
            }
            if (act1) {
                if (b1 > t)      { sel1 = true; act1 = false; }
                else if (b1 < t) { act1 = false; }
            }
            if (tid == 0) s_remk = remk - s_gt;
            __syncthreads();
        }

        // ties at K-th value: lowest node index wins (jax.lax.top_k tie-break).
        {
            const unsigned mA = __ballot_sync(0xffffffffu, act0);
            const unsigned mB = __ballot_sync(0xffffffffu, act1);
            if (lane == 0) { s_wA[warp] = __popc(mA); s_wB[warp] = __popc(mB); }
            __syncthreads();
            if (tid == 0) {
                int run = 0;
                #pragma unroll
                for (int i = 0; i < 8; i++) { s_pA[i] = run; run += s_wA[i]; }
                #pragma unroll
                for (int i = 0; i < 8; i++) { s_pB[i] = run; run += s_wB[i]; }
            }
            __syncthreads();
            const unsigned remk = s_remk;
            const unsigned lt = (1u << lane) - 1u;
            if (act0 && (unsigned)(s_pA[warp] + __popc(mA & lt)) < remk) sel0 = true;
            if (act1 && (unsigned)(s_pB[warp] + __popc(mB & lt)) < remk) sel1 = true;
            __syncthreads();
        }

        // deterministic compaction ordered by node index (set A then set B)
        {
            const unsigned cA = __ballot_sync(0xffffffffu, sel0);
            const unsigned cB = __ballot_sync(0xffffffffu, sel1);
            if (lane == 0) { s_wA[warp] = __popc(cA); s_wB[warp] = __popc(cB); }
            __syncthreads();
            if (tid == 0) {
                int run = 0;
                #pragma unroll
                for (int i = 0; i < 8; i++) { s_pA[i] = run; run += s_wA[i]; }
                #pragma unroll
                for (int i = 0; i < 8; i++) { s_pB[i] = run; run += s_wB[i]; }
            }
            __syncthreads();
            const float inv = s_inv;
            const unsigned lt = (1u << lane) - 1u;
            if (sel0) {
                const int slot = s_pA[warp] + __popc(cA & lt);
                g_sel[b * KK + slot] = make_int2(tid, __float_as_int(tanhf(s0v * inv)));
            }
            if (sel1) {
                const int slot = s_pB[warp] + __popc(cB & lt);
                g_sel[b * KK + slot] = make_int2(tid + 256, __float_as_int(tanhf(s1v * inv)));
            }
        }
        __threadfence();
        __syncthreads();
        if (tid == 0) atomicExch(&g_flag[b], 1);   // publish
    } else {
        // consumers: wait until this graph's selection is published
        if (tid == 0) {
            while (atomicAdd(&g_flag[b], 0) == 0) { }
        }
        __syncthreads();
        __threadfence();
    }

    // ---- gather: chunk c accumulates rows [c*64, c*64+64) ----
    if (tid < 64) s_sel[tid] = g_sel[b * KK + c * 64 + tid];
    __syncthreads();

    const float* xb = x + (size_t)b * NN * DD + tid;
    float a0 = 0.f, a1 = 0.f, a2 = 0.f, a3 = 0.f;
    #pragma unroll 16
    for (int k = 0; k < 64; k += 4) {
        const int2 p0 = s_sel[k];
        const int2 p1 = s_sel[k + 1];
        const int2 p2 = s_sel[k + 2];
        const int2 p3 = s_sel[k + 3];
        a0 += xb[(size_t)p0.x * DD] * __int_as_float(p0.y);
        a1 += xb[(size_t)p1.x * DD] * __int_as_float(p1.y);
        a2 += xb[(size_t)p2.x * DD] * __int_as_float(p2.y);
        a3 += xb[(size_t)p3.x * DD] * __int_as_float(p3.y);
    }
    g_part[blockIdx.x * DD + tid] = (a0 + a1) + (a2 + a3);

    // last arriver folds partials (fixed slots, fixed order -> deterministic)
    __threadfence();
    __syncthreads();
    if (tid == 0) s_last = (atomicAdd(&g_cnt[b], 1) == 3);
    __syncthreads();
    if (s_last) {
        if (tid == 0) { g_cnt[b] = 0; g_flag[b] = 0; }   // self-reset for replay
        const float* p = g_part + b * 4 * DD;
        const float v = (p[tid] + p[DD + tid]) + (p[2 * DD + tid] + p[3 * DD + tid]);
        out[b * DD + tid] = v * (1.0f / (float)KK);
    }
}

extern "C" void kernel_launch(void* const* d_in, const int* in_sizes, int n_in,
                              void* d_out, int out_size)
{
    (void)in_sizes; (void)n_in; (void)out_size;
    const float* x = (const float*)d_in[0];
    const float* w = (const float*)d_in[1];
    float* out = (float*)d_out;

    score_kernel<<<(BB * NN) / 16, 256>>>(x, w);
    select_gather_kernel<<<BB * 4, 256>>>(x, w, out);
}

// round 15
// speedup vs baseline: 1.1057x; 1.1057x over previous
#include <cuda_runtime.h>
#include <cuda_bf16.h>

// TopKPool_16372415332892
// out[b] = (1/K) * sum_{topK rows} x[row] * tanh((x[row].w)/||w||)
// B=256, N=512, D=256, K=256. edge_index/batch dead inputs.

#define BB 256
#define NN 512
#define DD 256
#define KK 256

__device__ float g_score[BB * NN];     // raw dot products (selection monotone in this)
__device__ int2  g_sel[BB * KK];       // {node idx, gate bits}, compacted by node order
__device__ float g_part[BB * 4 * DD];  // gather partials (4 chunks/graph)
__device__ int   g_cnt[BB];            // gather->fold arrival counters (self-resetting)

// ---------------- Kernel 1: persistent score kernel ----------------
// grid = 1024 blocks (single co-resident wave), 256 threads (8 warps).
// Block i owns contiguous rows [i*128, i*128+128): 8 iterations x 16 rows,
// 2 rows/warp/iter, unroll 2 -> 8 independent LDG.128 in flight per warp.
__global__ __launch_bounds__(256)
void score_kernel(const float* __restrict__ x, const float* __restrict__ w)
{
    if (blockIdx.x == 0 && threadIdx.x < BB) g_cnt[threadIdx.x] = 0;

    const int lane = threadIdx.x & 31;
    const int warp = threadIdx.x >> 5;

    const float4 wa = *reinterpret_cast<const float4*>(w + lane * 4);
    const float4 wb = *reinterpret_cast<const float4*>(w + 128 + lane * 4);

    const int base = blockIdx.x * 128 + warp * 2;   // this warp's first row

    #pragma unroll 2
    for (int it = 0; it < 8; ++it) {
        const int row0 = base + it * 16;
        const float* r0 = x + (size_t)row0 * DD;
        const float* r1 = r0 + DD;
        const float4 a0 = *reinterpret_cast<const float4*>(r0 + lane * 4);
        const float4 c0 = *reinterpret_cast<const float4*>(r0 + 128 + lane * 4);
        const float4 a1 = *reinterpret_cast<const float4*>(r1 + lane * 4);
        const float4 c1 = *reinterpret_cast<const float4*>(r1 + 128 + lane * 4);

        float d0 = a0.x * wa.x + a0.y * wa.y + a0.z * wa.z + a0.w * wa.w
                 + c0.x * wb.x + c0.y * wb.y + c0.z * wb.z + c0.w * wb.w;
        float d1 = a1.x * wa.x + a1.y * wa.y + a1.z * wa.z + a1.w * wa.w
                 + c1.x * wb.x + c1.y * wb.y + c1.z * wb.z + c1.w * wb.w;
        #pragma unroll
        for (int o = 16; o; o >>= 1) {
            d0 += __shfl_xor_sync(0xffffffffu, d0, o);
            d1 += __shfl_xor_sync(0xffffffffu, d1, o);
        }
        if (lane == 0) {
            *reinterpret_cast<float2*>(g_score + row0) = make_float2(d0, d1);
        }
    }
}

// ---------------- Kernel 2: radix top-K select (block per graph, 256 thr) ----------------
// Thread tid owns nodes tid and tid+256. 4 passes of 8-bit histogram radix-select
// over ordered-uint keys, then exact lowest-index tie-break (jax.lax.top_k).
__global__ __launch_bounds__(256)
void rank_kernel(const float* __restrict__ w)
{
    __shared__ unsigned hist[256];
    __shared__ unsigned sscan[256];   // sscan[v] = # active nodes with byte >= v
    __shared__ unsigned s_t, s_gt, s_remk;
    __shared__ int s_wA[8], s_wB[8], s_pA[8], s_pB[8];
    __shared__ float s_inv;

    const int tid  = threadIdx.x;
    const int lane = tid & 31;
    const int warp = tid >> 5;
    const int b    = blockIdx.x;

    if (warp == 0) {
        float ssq = 0.f;
        #pragma unroll
        for (int i = 0; i < 8; i++) { float v = w[lane + i * 32]; ssq += v * v; }
        #pragma unroll
        for (int o = 16; o; o >>= 1) ssq += __shfl_xor_sync(0xffffffffu, ssq, o);
        if (lane == 0) s_inv = rsqrtf(ssq);
    }
    if (tid == 0) s_remk = KK;

    const float* sc = g_score + b * NN;
    const float s0v = sc[tid];
    const float s1v = sc[tid + 256];
    const unsigned bits0 = __float_as_uint(s0v);
    const unsigned bits1 = __float_as_uint(s1v);
    const unsigned key0 = (bits0 & 0x80000000u) ? ~bits0 : (bits0 | 0x80000000u);
    const unsigned key1 = (bits1 & 0x80000000u) ? ~bits1 : (bits1 | 0x80000000u);

    bool act0 = true, act1 = true, sel0 = false, sel1 = false;

    #pragma unroll
    for (int pass = 0; pass < 4; ++pass) {
        hist[tid] = 0u;
        __syncthreads();
        const unsigned b0 = (key0 >> (24 - 8 * pass)) & 0xFFu;
        const unsigned b1 = (key1 >> (24 - 8 * pass)) & 0xFFu;
        if (act0) atomicAdd(&hist[b0], 1u);
        if (act1) atomicAdd(&hist[b1], 1u);
        __syncthreads();

        // suffix scan of hist by warp 0: lane l owns bins [8l, 8l+8)
        if (warp == 0) {
            unsigned tot = 0;
            #pragma unroll
            for (int j = 0; j < 8; j++) tot += hist[lane * 8 + j];
            unsigned suf = tot;
            #pragma unroll
            for (int o = 1; o < 32; o <<= 1) {
                unsigned t2 = __shfl_down_sync(0xffffffffu, suf, o);
                if (lane + o < 32) suf += t2;
            }
            unsigned run = suf - tot;
            #pragma unroll
            for (int j = 7; j >= 0; --j) {
                run += hist[lane * 8 + j];
                sscan[lane * 8 + j] = run;
            }
        }
        __syncthreads();

        const unsigned remk = s_remk;
        {
            const unsigned ge = sscan[tid];
            const unsigned gt = (tid == 255) ? 0u : sscan[tid + 1];
            if (ge >= remk && gt < remk) { s_t = (unsigned)tid; s_gt = gt; }
        }
        __syncthreads();

        const unsigned t = s_t;
        if (act0) {
            if (b0 > t)      { sel0 = true; act0 = false; }
            else if (b0 < t) { act0 = false; }
        }
        if (act1) {
            if (b1 > t)      { sel1 = true; act1 = false; }
            else if (b1 < t) { act1 = false; }
        }
        if (tid == 0) s_remk = remk - s_gt;
        __syncthreads();
    }

    // ties at the K-th value: lowest node indices win.
    // Set A = nodes [0,256) (owner tid), set B = nodes [256,512).
    {
        const unsigned mA = __ballot_sync(0xffffffffu, act0);
        const unsigned mB = __ballot_sync(0xffffffffu, act1);
        if (lane == 0) { s_wA[warp] = __popc(mA); s_wB[warp] = __popc(mB); }
        __syncthreads();
        if (tid == 0) {
            int run = 0;
            #pragma unroll
            for (int i = 0; i < 8; i++) { s_pA[i] = run; run += s_wA[i]; }
            #pragma unroll
            for (int i = 0; i < 8; i++) { s_pB[i] = run; run += s_wB[i]; }
        }
        __syncthreads();
        const unsigned remk = s_remk;
        const unsigned lt = (1u << lane) - 1u;
        if (act0 && (unsigned)(s_pA[warp] + __popc(mA & lt)) < remk) sel0 = true;
        if (act1 && (unsigned)(s_pB[warp] + __popc(mB & lt)) < remk) sel1 = true;
        __syncthreads();
    }

    // deterministic compaction ordered by node index (A then B)
    {
        const unsigned cA = __ballot_sync(0xffffffffu, sel0);
        const unsigned cB = __ballot_sync(0xffffffffu, sel1);
        if (lane == 0) { s_wA[warp] = __popc(cA); s_wB[warp] = __popc(cB); }
        __syncthreads();
        if (tid == 0) {
            int run = 0;
            #pragma unroll
            for (int i = 0; i < 8; i++) { s_pA[i] = run; run += s_wA[i]; }
            #pragma unroll
            for (int i = 0; i < 8; i++) { s_pB[i] = run; run += s_wB[i]; }
        }
        __syncthreads();
        const float inv = s_inv;
        const unsigned lt = (1u << lane) - 1u;
        if (sel0) {
            const int slot = s_pA[warp] + __popc(cA & lt);
            g_sel[b * KK + slot] = make_int2(tid, __float_as_int(tanhf(s0v * inv)));
        }
        if (sel1) {
            const int slot = s_pB[warp] + __popc(cB & lt);
            g_sel[b * KK + slot] = make_int2(tid + 256, __float_as_int(tanhf(s1v * inv)));
        }
    }
}

// ---------------- Kernel 3: gather (4 blocks/graph) + last-block fold ----------------
__global__ __launch_bounds__(256)
void gather_kernel(const float* __restrict__ x, float* __restrict__ out)
{
    __shared__ int2 s_sel[64];
    __shared__ int  s_last;

    const int tid = threadIdx.x;
    const int b   = blockIdx.x >> 2;
    const int c   = blockIdx.x & 3;

    if (tid < 64) s_sel[tid] = g_sel[b * KK + c * 64 + tid];
    __syncthreads();

    const float* xb = x + (size_t)b * NN * DD + tid;
    float a0 = 0.f, a1 = 0.f, a2 = 0.f, a3 = 0.f;
    #pragma unroll 16
    for (int k = 0; k < 64; k += 4) {
        const int2 p0 = s_sel[k];
        const int2 p1 = s_sel[k + 1];
        const int2 p2 = s_sel[k + 2];
        const int2 p3 = s_sel[k + 3];
        a0 += xb[(size_t)p0.x * DD] * __int_as_float(p0.y);
        a1 += xb[(size_t)p1.x * DD] * __int_as_float(p1.y);
        a2 += xb[(size_t)p2.x * DD] * __int_as_float(p2.y);
        a3 += xb[(size_t)p3.x * DD] * __int_as_float(p3.y);
    }
    g_part[blockIdx.x * DD + tid] = (a0 + a1) + (a2 + a3);

    // last block of this graph folds partials (fixed slots, fixed order -> deterministic)
    __threadfence();
    __syncthreads();
    if (tid == 0) s_last = (atomicAdd(&g_cnt[b], 1) == 3);
    __syncthreads();
    if (s_last) {
        if (tid == 0) g_cnt[b] = 0;   // self-reset for graph replay
        const float* p = g_part + b * 4 * DD;
        const float v = (p[tid] + p[DD + tid]) + (p[2 * DD + tid] + p[3 * DD + tid]);
        out[b * DD + tid] = v * (1.0f / (float)KK);
    }
}

extern "C" void kernel_launch(void* const* d_in, const int* in_sizes, int n_in,
                              void* d_out, int out_size)
{
    (void)in_sizes; (void)n_in; (void)out_size;
    const float* x = (const float*)d_in[0];
    const float* w = (const float*)d_in[1];
    float* out = (float*)d_out;

    score_kernel<<<1024, 256>>>(x, w);
    rank_kernel<<<BB, 256>>>(w);
    gather_kernel<<<BB * 4, 256>>>(x, out);
}

// round 16
// speedup vs baseline: 1.2319x; 1.1141x over previous
#include <cuda_runtime.h>
#include <cuda_bf16.h>

// TopKPool_16372415332892
// out[b] = (1/K) * sum_{topK rows} x[row] * tanh((x[row].w)/||w||)
// B=256, N=512, D=256, K=256. edge_index/batch dead inputs.

#define BB 256
#define NN 512
#define DD 256
#define KK 256

__device__ float g_score[BB * NN];     // raw dot products (selection monotone in this)
__device__ float g_part[BB * 4 * DD];  // gather partials (4 chunks/graph)
__device__ int   g_cnt[BB];            // gather->fold arrival counters (self-resetting)

// ---------------- Kernel 1: scores (2 rows/warp, wide grid — R11-proven) ----------------
// grid = B*N/16 = 8192 blocks, 256 threads. Block 0 zeroes fold counters.
__global__ __launch_bounds__(256)
void score_kernel(const float* __restrict__ x, const float* __restrict__ w)
{
    if (blockIdx.x == 0 && threadIdx.x < BB) g_cnt[threadIdx.x] = 0;

    const int lane = threadIdx.x & 31;
    const int warp = threadIdx.x >> 5;
    const int row0 = blockIdx.x * 16 + warp * 2;

    const float4 wa = *reinterpret_cast<const float4*>(w + lane * 4);
    const float4 wb = *reinterpret_cast<const float4*>(w + 128 + lane * 4);

    const float* r0 = x + (size_t)row0 * DD;
    const float* r1 = r0 + DD;
    const float4 a0 = *reinterpret_cast<const float4*>(r0 + lane * 4);
    const float4 c0 = *reinterpret_cast<const float4*>(r0 + 128 + lane * 4);
    const float4 a1 = *reinterpret_cast<const float4*>(r1 + lane * 4);
    const float4 c1 = *reinterpret_cast<const float4*>(r1 + 128 + lane * 4);

    float d0 = a0.x * wa.x + a0.y * wa.y + a0.z * wa.z + a0.w * wa.w
             + c0.x * wb.x + c0.y * wb.y + c0.z * wb.z + c0.w * wb.w;
    float d1 = a1.x * wa.x + a1.y * wa.y + a1.z * wa.z + a1.w * wa.w
             + c1.x * wb.x + c1.y * wb.y + c1.z * wb.z + c1.w * wb.w;
    #pragma unroll
    for (int o = 16; o; o >>= 1) {
        d0 += __shfl_xor_sync(0xffffffffu, d0, o);
        d1 += __shfl_xor_sync(0xffffffffu, d1, o);
    }
    if (lane == 0) {
        g_score[row0]     = d0;
        g_score[row0 + 1] = d1;
    }
}

// ---------------- Kernel 2: redundant select + gather + fold ----------------
// grid = B*4 blocks, 256 threads. Each block INDEPENDENTLY runs the radix
// top-K select for its graph (reads 2KB of g_score; bitwise-identical result
// across the graph's 4 blocks -> deterministic), keeps the selection in smem,
// gathers its 64-row chunk, and the last arriver folds partials into out.
// No inter-block waits except the proven cheap fold counter.
__global__ __launch_bounds__(256)
void select_gather_kernel(const float* __restrict__ x,
                          const float* __restrict__ w,
                          float* __restrict__ out)
{
    __shared__ unsigned hist[256];
    __shared__ unsigned sscan[256];   // sscan[v] = # active nodes with byte >= v
    __shared__ unsigned s_t, s_gt, s_remk;
    __shared__ int s_wA[8], s_wB[8], s_pA[8], s_pB[8];
    __shared__ float s_inv;
    __shared__ int2 s_all[KK];        // full compacted selection for this graph
    __shared__ int  s_last;

    const int tid  = threadIdx.x;
    const int lane = tid & 31;
    const int warp = tid >> 5;
    const int b    = blockIdx.x >> 2;
    const int c    = blockIdx.x & 3;

    // ---- ||w||^-1 ----
    if (warp == 0) {
        float ssq = 0.f;
        #pragma unroll
        for (int i = 0; i < 8; i++) { float v = w[lane + i * 32]; ssq += v * v; }
        #pragma unroll
        for (int o = 16; o; o >>= 1) ssq += __shfl_xor_sync(0xffffffffu, ssq, o);
        if (lane == 0) s_inv = rsqrtf(ssq);
    }
    if (tid == 0) s_remk = KK;

    // ---- radix top-K select: thread owns nodes tid and tid+256 ----
    const float* sc = g_score + b * NN;
    const float s0v = sc[tid];
    const float s1v = sc[tid + 256];
    const unsigned bits0 = __float_as_uint(s0v);
    const unsigned bits1 = __float_as_uint(s1v);
    const unsigned key0 = (bits0 & 0x80000000u) ? ~bits0 : (bits0 | 0x80000000u);
    const unsigned key1 = (bits1 & 0x80000000u) ? ~bits1 : (bits1 | 0x80000000u);

    bool act0 = true, act1 = true, sel0 = false, sel1 = false;

    #pragma unroll
    for (int pass = 0; pass < 4; ++pass) {
        hist[tid] = 0u;
        __syncthreads();
        const unsigned b0 = (key0 >> (24 - 8 * pass)) & 0xFFu;
        const unsigned b1 = (key1 >> (24 - 8 * pass)) & 0xFFu;
        if (act0) atomicAdd(&hist[b0], 1u);
        if (act1) atomicAdd(&hist[b1], 1u);
        __syncthreads();

        // suffix scan of hist by warp 0: lane l owns bins [8l, 8l+8)
        if (warp == 0) {
            unsigned tot = 0;
            #pragma unroll
            for (int j = 0; j < 8; j++) tot += hist[lane * 8 + j];
            unsigned suf = tot;
            #pragma unroll
            for (int o = 1; o < 32; o <<= 1) {
                unsigned t2 = __shfl_down_sync(0xffffffffu, suf, o);
                if (lane + o < 32) suf += t2;
            }
            unsigned run = suf - tot;
            #pragma unroll
            for (int j = 7; j >= 0; --j) {
                run += hist[lane * 8 + j];
                sscan[lane * 8 + j] = run;
            }
        }
        __syncthreads();

        const unsigned remk = s_remk;
        {
            const unsigned ge = sscan[tid];
            const unsigned gt = (tid == 255) ? 0u : sscan[tid + 1];
            if (ge >= remk && gt < remk) { s_t = (unsigned)tid; s_gt = gt; }
        }
        __syncthreads();

        const unsigned t = s_t;
        if (act0) {
            if (b0 > t)      { sel0 = true; act0 = false; }
            else if (b0 < t) { act0 = false; }
        }
        if (act1) {
            if (b1 > t)      { sel1 = true; act1 = false; }
            else if (b1 < t) { act1 = false; }
        }
        if (tid == 0) s_remk = remk - s_gt;
        __syncthreads();
    }

    // ties at the K-th value: lowest node indices win (jax.lax.top_k tie-break).
    // Set A = nodes [0,256) (owner tid), set B = nodes [256,512).
    {
        const unsigned mA = __ballot_sync(0xffffffffu, act0);
        const unsigned mB = __ballot_sync(0xffffffffu, act1);
        if (lane == 0) { s_wA[warp] = __popc(mA); s_wB[warp] = __popc(mB); }
        __syncthreads();
        if (tid == 0) {
            int run = 0;
            #pragma unroll
            for (int i = 0; i < 8; i++) { s_pA[i] = run; run += s_wA[i]; }
            #pragma unroll
            for (int i = 0; i < 8; i++) { s_pB[i] = run; run += s_wB[i]; }
        }
        __syncthreads();
        const unsigned remk = s_remk;
        const unsigned lt = (1u << lane) - 1u;
        if (act0 && (unsigned)(s_pA[warp] + __popc(mA & lt)) < remk) sel0 = true;
        if (act1 && (unsigned)(s_pB[warp] + __popc(mB & lt)) < remk) sel1 = true;
        __syncthreads();
    }

    // deterministic compaction into smem, ordered by node index (A then B)
    {
        const unsigned cA = __ballot_sync(0xffffffffu, sel0);
        const unsigned cB = __ballot_sync(0xffffffffu, sel1);
        if (lane == 0) { s_wA[warp] = __popc(cA); s_wB[warp] = __popc(cB); }
        __syncthreads();
        if (tid == 0) {
            int run = 0;
            #pragma unroll
            for (int i = 0; i < 8; i++) { s_pA[i] = run; run += s_wA[i]; }
            #pragma unroll
            for (int i = 0; i < 8; i++) { s_pB[i] = run; run += s_wB[i]; }
        }
        __syncthreads();
        const float inv = s_inv;
        const unsigned lt = (1u << lane) - 1u;
        if (sel0) {
            const int slot = s_pA[warp] + __popc(cA & lt);
            s_all[slot] = make_int2(tid, __float_as_int(tanhf(s0v * inv)));
        }
        if (sel1) {
            const int slot = s_pB[warp] + __popc(cB & lt);
            s_all[slot] = make_int2(tid + 256, __float_as_int(tanhf(s1v * inv)));
        }
    }
    __syncthreads();

    // ---- gather: chunk c accumulates rows [c*64, c*64+64) ----
    const float* xb = x + (size_t)b * NN * DD + tid;
    float a0 = 0.f, a1 = 0.f, a2 = 0.f, a3 = 0.f;
    const int k0 = c * 64;
    #pragma unroll 16
    for (int k = k0; k < k0 + 64; k += 4) {
        const int2 p0 = s_all[k];
        const int2 p1 = s_all[k + 1];
        const int2 p2 = s_all[k + 2];
        const int2 p3 = s_all[k + 3];
        a0 += xb[(size_t)p0.x * DD] * __int_as_float(p0.y);
        a1 += xb[(size_t)p1.x * DD] * __int_as_float(p1.y);
        a2 += xb[(size_t)p2.x * DD] * __int_as_float(p2.y);
        a3 += xb[(size_t)p3.x * DD] * __int_as_float(p3.y);
    }
    g_part[blockIdx.x * DD + tid] = (a0 + a1) + (a2 + a3);

    // last block of this graph folds partials (fixed slots, fixed order -> deterministic)
    __threadfence();
    __syncthreads();
    if (tid == 0) s_last = (atomicAdd(&g_cnt[b], 1) == 3);
    __syncthreads();
    if (s_last) {
        if (tid == 0) g_cnt[b] = 0;   // self-reset for graph replay
        const float* p = g_part + b * 4 * DD;
        const float v = (p[tid] + p[DD + tid]) + (p[2 * DD + tid] + p[3 * DD + tid]);
        out[b * DD + tid] = v * (1.0f / (float)KK);
    }
}

extern "C" void kernel_launch(void* const* d_in, const int* in_sizes, int n_in,
                              void* d_out, int out_size)
{
    (void)in_sizes; (void)n_in; (void)out_size;
    const float* x = (const float*)d_in[0];
    const float* w = (const float*)d_in[1];
    float* out = (float*)d_out;

    score_kernel<<<(BB * NN) / 16, 256>>>(x, w);
    select_gather_kernel<<<BB * 4, 256>>>(x, w, out);
}